// round 8
// baseline (speedup 1.0000x reference)
#include <cuda_runtime.h>
#include <cuda_fp16.h>
#include <math.h>

#define BB     8192
#define MM     200
#define EE     64
#define NOTHER 128
#define H1     96
#define F1     128
#define F2     85
#define F3     64

__device__ float g_tmp[BB * EE];

typedef unsigned long long ull;
__device__ __forceinline__ ull pk2(float lo, float hi) {
    ull r; asm("mov.b64 %0, {%1, %2};" : "=l"(r) : "f"(lo), "f"(hi)); return r;
}
__device__ __forceinline__ void upk2(ull v, float& lo, float& hi) {
    asm("mov.b64 {%0, %1}, %2;" : "=f"(lo), "=f"(hi) : "l"(v));
}
__device__ __forceinline__ ull fma2(ull a, ull b, ull c) {
    ull d; asm("fma.rn.f32x2 %0, %1, %2, %3;" : "=l"(d) : "l"(a), "l"(b), "l"(c)); return d;
}

// ---------------- Kernel 1: attention + weighted sum (unchanged) ----------------
#define SM1_U32  (3328 + 7488 + 720)
#define SM1_BYTES (SM1_U32 * 4)

__global__ __launch_bounds__(256, 4)
void din_attn(const float* __restrict__ hist, const float* __restrict__ target,
              const float* __restrict__ aW1, const float* __restrict__ ab1,
              const float* __restrict__ aW2, const float* __restrict__ ab2)
{
    extern __shared__ unsigned sm1[];
    unsigned* s_W2 = sm1;
    unsigned* s_h  = sm1 + 3328;
    float* s_tgt  = (float*)(sm1 + 3328 + 7488);
    float* s_c    = s_tgt + 64;
    float* s_w2   = s_c + 96;
    float* s_aij  = s_w2 + 96;
    float* s_part = s_aij + 208;

    const int b = blockIdx.x;
    const int t = threadIdx.x;
    const float* hb = hist + (size_t)b * MM * EE;

    if (t < EE) s_tgt[t] = target[(size_t)b * EE + t];
    if (t < H1) s_w2[t]  = aW2[t];
    __syncthreads();

    for (int idx = t; idx < MM * 16; idx += 256) {
        const int row = idx >> 4, q = idx & 15;
        float4 v = ((const float4*)(hb + (size_t)row * EE))[q];
        __half2 h01 = __floats2half2_rn(v.x, v.y);
        __half2 h23 = __floats2half2_rn(v.z, v.w);
        uint2 st;
        st.x = *(unsigned*)&h01;
        st.y = *(unsigned*)&h23;
        *(uint2*)(s_h + row * 36 + 2 * q) = st;
    }
    for (int idx = t; idx < 8 * 36; idx += 256)
        s_h[200 * 36 + idx] = 0u;

    for (int idx = t; idx < 32 * H1; idx += 256) {
        const int k2 = idx / H1, n = idx - k2 * H1;
        const int e0 = 2 * k2, e1 = 2 * k2 + 1;
        float v0 = aW1[e0 * H1 + n] + s_tgt[e0] * aW1[(EE + e0) * H1 + n];
        float v1 = aW1[e1 * H1 + n] + s_tgt[e1] * aW1[(EE + e1) * H1 + n];
        __half2 p = __floats2half2_rn(v0, v1);
        s_W2[k2 * 104 + n] = *(unsigned*)&p;
    }
    if (t < H1) {
        float acc = ab1[t];
        #pragma unroll 8
        for (int e = 0; e < EE; e++)
            acc = fmaf(s_tgt[e], aW1[(2 * EE + e) * H1 + t], acc);
        s_c[t] = acc;
    }
    __syncthreads();

    const int warp = t >> 5, lane = t & 31;
    const int gid = lane >> 2, tig = lane & 3;
    const float bias2 = ab2[0];

    for (int mt = warp; mt < 13; mt += 8) {
        unsigned A[4][4];
        const unsigned* hp = s_h + (mt * 16 + gid) * 36 + tig;
        #pragma unroll
        for (int ks = 0; ks < 4; ks++) {
            A[ks][0] = hp[8 * ks];
            A[ks][1] = hp[288 + 8 * ks];
            A[ks][2] = hp[8 * ks + 4];
            A[ks][3] = hp[288 + 8 * ks + 4];
        }

        float aij0 = 0.f, aij1 = 0.f;
        const unsigned* wb = s_W2 + tig * 104 + gid;

        #pragma unroll 1
        for (int nt = 0; nt < 12; nt++) {
            float c0 = 0.f, c1 = 0.f, c2 = 0.f, c3 = 0.f;
            #pragma unroll
            for (int ks = 0; ks < 4; ks++) {
                const unsigned b0 = wb[ks * 832 + nt * 8];
                const unsigned b1 = wb[ks * 832 + 416 + nt * 8];
                asm volatile(
                    "mma.sync.aligned.m16n8k16.row.col.f32.f16.f16.f32 "
                    "{%0,%1,%2,%3}, {%4,%5,%6,%7}, {%8,%9}, {%0,%1,%2,%3};"
                    : "+f"(c0), "+f"(c1), "+f"(c2), "+f"(c3)
                    : "r"(A[ks][0]), "r"(A[ks][1]), "r"(A[ks][2]), "r"(A[ks][3]),
                      "r"(b0), "r"(b1));
            }
            const int j0 = nt * 8 + 2 * tig;
            const float cc0 = s_c[j0],  cc1 = s_c[j0 + 1];
            const float w0  = s_w2[j0], w1  = s_w2[j0 + 1];
            aij0 = fmaf(fmaxf(c0 + cc0, 0.f), w0, aij0);
            aij0 = fmaf(fmaxf(c1 + cc1, 0.f), w1, aij0);
            aij1 = fmaf(fmaxf(c2 + cc0, 0.f), w0, aij1);
            aij1 = fmaf(fmaxf(c3 + cc1, 0.f), w1, aij1);
        }
        aij0 += __shfl_xor_sync(0xffffffffu, aij0, 1);
        aij0 += __shfl_xor_sync(0xffffffffu, aij0, 2);
        aij1 += __shfl_xor_sync(0xffffffffu, aij1, 1);
        aij1 += __shfl_xor_sync(0xffffffffu, aij1, 2);
        if (tig == 0) {
            const int r0 = mt * 16 + gid;
            if (r0 < MM)     s_aij[r0]     = aij0 + bias2;
            if (r0 + 8 < MM) s_aij[r0 + 8] = aij1 + bias2;
        }
    }
    __syncthreads();

    {
        const int chunk = t >> 6, e = t & 63;
        const int m0 = chunk * 50;
        float acc = 0.f;
        #pragma unroll 5
        for (int m = m0; m < m0 + 50; m++)
            acc = fmaf(s_aij[m], hb[(size_t)m * EE + e], acc);
        s_part[chunk * EE + e] = acc;
    }
    __syncthreads();
    if (t < EE)
        g_tmp[(size_t)b * EE + t] =
            s_part[t] + s_part[EE + t] + s_part[2 * EE + t] + s_part[3 * EE + t];
}

// ---------------- Kernel 2: MLP v4 — j-sliced warps, transposed activations, f32x2 ----
// smem floats: xT[256][36], h1T[128][36], h2T[85][36], fin[32][33]
#define XT_OFF  0
#define H1T_OFF (XT_OFF + 256 * 36)
#define H2T_OFF (H1T_OFF + 128 * 36)
#define FIN_OFF (H2T_OFF + 85 * 36)
#define SM2_FLOATS (FIN_OFF + 32 * 33)
#define SM2_BYTES (SM2_FLOATS * 4)

__global__ __launch_bounds__(256)
void din_mlp(const float* __restrict__ target, const float* __restrict__ other,
             const float* __restrict__ oW1, const float* __restrict__ ob1,
             const float* __restrict__ oW2, const float* __restrict__ ob2,
             const float* __restrict__ oW3, const float* __restrict__ ob3,
             const float* __restrict__ fW,  const float* __restrict__ fb,
             float* __restrict__ out)
{
    extern __shared__ float sm2[];
    float* xT  = sm2 + XT_OFF;    // [k][b] stride 36
    float* h1T = sm2 + H1T_OFF;   // [j][b] stride 36
    float* h2T = sm2 + H2T_OFF;   // [j][b] stride 36
    float* fin = sm2 + FIN_OFF;   // [b][33]

    const int t = threadIdx.x;
    const int B0 = blockIdx.x * 32;

    // ---- stage x transposed: k in {tmp 0-63 | target 64-127 | other 128-255} ----
    for (int idx = t; idx < 32 * 64; idx += 256) {
        const int b = idx >> 6, k = idx & 63;
        xT[k * 36 + b]        = g_tmp[(size_t)(B0 + b) * EE + k];
        xT[(64 + k) * 36 + b] = target[(size_t)(B0 + b) * EE + k];
    }
    for (int idx = t; idx < 32 * 128; idx += 256) {
        const int b = idx >> 7, k = idx & 127;
        xT[(128 + k) * 36 + b] = other[(size_t)(B0 + b) * NOTHER + k];
    }
    __syncthreads();

    const int warp = t >> 5, lane = t & 31;
    const int c   = lane & 3;        // j-column group
    const int b0  = (lane >> 2) * 4; // 4 batches (2 f32x2 pairs)

    // ---- Layer 1: 256 -> 128 ; warp owns j in [16w,16w+16), thread 4j x 4b ----
    {
        const int j0 = warp * 16 + c * 4;
        ull a00, a01, a10, a11, a20, a21, a30, a31;
        {
            const float4 bz = *(const float4*)(ob1 + j0);
            a00 = a01 = pk2(bz.x, bz.x);
            a10 = a11 = pk2(bz.y, bz.y);
            a20 = a21 = pk2(bz.z, bz.z);
            a30 = a31 = pk2(bz.w, bz.w);
        }
        #pragma unroll 4
        for (int k = 0; k < 256; k++) {
            const float4 xv = *(const float4*)(xT + k * 36 + b0);
            const ull px0 = pk2(xv.x, xv.y);
            const ull px1 = pk2(xv.z, xv.w);
            const float4 wv = *(const float4*)(oW1 + k * F1 + j0);
            const ull w0 = pk2(wv.x, wv.x), w1 = pk2(wv.y, wv.y);
            const ull w2 = pk2(wv.z, wv.z), w3 = pk2(wv.w, wv.w);
            a00 = fma2(w0, px0, a00); a01 = fma2(w0, px1, a01);
            a10 = fma2(w1, px0, a10); a11 = fma2(w1, px1, a11);
            a20 = fma2(w2, px0, a20); a21 = fma2(w2, px1, a21);
            a30 = fma2(w3, px0, a30); a31 = fma2(w3, px1, a31);
        }
        float l0, h0, l1, h1;
        float4 r;
        upk2(a00, l0, h0); upk2(a01, l1, h1);
        r.x = fmaxf(l0, 0.f); r.y = fmaxf(h0, 0.f); r.z = fmaxf(l1, 0.f); r.w = fmaxf(h1, 0.f);
        *(float4*)(h1T + (j0 + 0) * 36 + b0) = r;
        upk2(a10, l0, h0); upk2(a11, l1, h1);
        r.x = fmaxf(l0, 0.f); r.y = fmaxf(h0, 0.f); r.z = fmaxf(l1, 0.f); r.w = fmaxf(h1, 0.f);
        *(float4*)(h1T + (j0 + 1) * 36 + b0) = r;
        upk2(a20, l0, h0); upk2(a21, l1, h1);
        r.x = fmaxf(l0, 0.f); r.y = fmaxf(h0, 0.f); r.z = fmaxf(l1, 0.f); r.w = fmaxf(h1, 0.f);
        *(float4*)(h1T + (j0 + 2) * 36 + b0) = r;
        upk2(a30, l0, h0); upk2(a31, l1, h1);
        r.x = fmaxf(l0, 0.f); r.y = fmaxf(h0, 0.f); r.z = fmaxf(l1, 0.f); r.w = fmaxf(h1, 0.f);
        *(float4*)(h1T + (j0 + 3) * 36 + b0) = r;
    }
    __syncthreads();

    // ---- Layer 2: 128 -> 85 ; warp owns j in [12w,12w+12), thread 3j x 4b ----
    {
        const int jb = warp * 12 + c * 3;
        const bool g0 = (jb < F2), g1 = (jb + 1 < F2), g2 = (jb + 2 < F2);
        ull a00, a01, a10, a11, a20, a21;
        a00 = a01 = g0 ? pk2(ob2[jb], ob2[jb]) : 0ull;
        a10 = a11 = g1 ? pk2(ob2[jb + 1], ob2[jb + 1]) : 0ull;
        a20 = a21 = g2 ? pk2(ob2[jb + 2], ob2[jb + 2]) : 0ull;
        #pragma unroll 4
        for (int k = 0; k < F1; k++) {
            const float4 xv = *(const float4*)(h1T + k * 36 + b0);
            const ull px0 = pk2(xv.x, xv.y);
            const ull px1 = pk2(xv.z, xv.w);
            const float* wr = oW2 + k * F2;
            const float w0f = g0 ? wr[jb] : 0.f;
            const float w1f = g1 ? wr[jb + 1] : 0.f;
            const float w2f = g2 ? wr[jb + 2] : 0.f;
            const ull w0 = pk2(w0f, w0f), w1 = pk2(w1f, w1f), w2 = pk2(w2f, w2f);
            a00 = fma2(w0, px0, a00); a01 = fma2(w0, px1, a01);
            a10 = fma2(w1, px0, a10); a11 = fma2(w1, px1, a11);
            a20 = fma2(w2, px0, a20); a21 = fma2(w2, px1, a21);
        }
        float l0, h0, l1, h1;
        float4 r;
        if (g0) {
            upk2(a00, l0, h0); upk2(a01, l1, h1);
            r.x = fmaxf(l0, 0.f); r.y = fmaxf(h0, 0.f); r.z = fmaxf(l1, 0.f); r.w = fmaxf(h1, 0.f);
            *(float4*)(h2T + (jb + 0) * 36 + b0) = r;
        }
        if (g1) {
            upk2(a10, l0, h0); upk2(a11, l1, h1);
            r.x = fmaxf(l0, 0.f); r.y = fmaxf(h0, 0.f); r.z = fmaxf(l1, 0.f); r.w = fmaxf(h1, 0.f);
            *(float4*)(h2T + (jb + 1) * 36 + b0) = r;
        }
        if (g2) {
            upk2(a20, l0, h0); upk2(a21, l1, h1);
            r.x = fmaxf(l0, 0.f); r.y = fmaxf(h0, 0.f); r.z = fmaxf(l1, 0.f); r.w = fmaxf(h1, 0.f);
            *(float4*)(h2T + (jb + 2) * 36 + b0) = r;
        }
    }
    __syncthreads();

    // ---- Layer 3: 85 -> 64 ; warp owns j in [8w,8w+8), thread 2j x 4b ; fold fW ----
    {
        const int jb = warp * 8 + c * 2;
        ull a00, a01, a10, a11;
        a00 = a01 = pk2(ob3[jb], ob3[jb]);
        a10 = a11 = pk2(ob3[jb + 1], ob3[jb + 1]);
        #pragma unroll 5
        for (int k = 0; k < F2; k++) {
            const float4 xv = *(const float4*)(h2T + k * 36 + b0);
            const ull px0 = pk2(xv.x, xv.y);
            const ull px1 = pk2(xv.z, xv.w);
            const float w0f = oW3[k * F3 + jb];
            const float w1f = oW3[k * F3 + jb + 1];
            const ull w0 = pk2(w0f, w0f), w1 = pk2(w1f, w1f);
            a00 = fma2(w0, px0, a00); a01 = fma2(w0, px1, a01);
            a10 = fma2(w1, px0, a10); a11 = fma2(w1, px1, a11);
        }
        const float f0 = fW[jb], f1 = fW[jb + 1];
        float l0, h0, l1, h1, m0, n0v, m1, n1v;
        upk2(a00, l0, h0); upk2(a01, l1, h1);   // j = jb,   b = b0..b0+3
        upk2(a10, m0, n0v); upk2(a11, m1, n1v); // j = jb+1
        float p0 = fmaxf(l0, 0.f) * f0 + fmaxf(m0, 0.f) * f1;
        float p1 = fmaxf(h0, 0.f) * f0 + fmaxf(n0v, 0.f) * f1;
        float p2 = fmaxf(l1, 0.f) * f0 + fmaxf(m1, 0.f) * f1;
        float p3 = fmaxf(h1, 0.f) * f0 + fmaxf(n1v, 0.f) * f1;
        const int col = warp * 4 + c;
        fin[(b0 + 0) * 33 + col] = p0;
        fin[(b0 + 1) * 33 + col] = p1;
        fin[(b0 + 2) * 33 + col] = p2;
        fin[(b0 + 3) * 33 + col] = p3;
    }
    __syncthreads();

    // ---- final reduce: 32 partials per batch ----
    {
        const int b = t >> 3, i = t & 7;
        float v = fin[b * 33 + i] + fin[b * 33 + i + 8]
                + fin[b * 33 + i + 16] + fin[b * 33 + i + 24];
        v += __shfl_down_sync(0xffffffffu, v, 4, 8);
        v += __shfl_down_sync(0xffffffffu, v, 2, 8);
        v += __shfl_down_sync(0xffffffffu, v, 1, 8);
        if (i == 0)
            out[B0 + b] = 1.f / (1.f + expf(-(v + fb[0])));
    }
}

extern "C" void kernel_launch(void* const* d_in, const int* in_sizes, int n_in,
                              void* d_out, int out_size)
{
    const float* hist   = (const float*)d_in[0];
    const float* target = (const float*)d_in[1];
    const float* other  = (const float*)d_in[2];
    const float* aW1    = (const float*)d_in[3];
    const float* ab1    = (const float*)d_in[4];
    const float* aW2    = (const float*)d_in[5];
    const float* ab2    = (const float*)d_in[6];
    const float* oW1    = (const float*)d_in[7];
    const float* ob1    = (const float*)d_in[8];
    const float* oW2    = (const float*)d_in[9];
    const float* ob2    = (const float*)d_in[10];
    const float* oW3    = (const float*)d_in[11];
    const float* ob3    = (const float*)d_in[12];
    const float* fW     = (const float*)d_in[13];
    const float* fb     = (const float*)d_in[14];
    float* out = (float*)d_out;

    static int configured = 0;
    if (!configured) {
        cudaFuncSetAttribute(din_mlp, cudaFuncAttributeMaxDynamicSharedMemorySize,
                             SM2_BYTES);
        configured = 1;
    }
    din_attn<<<BB, 256, SM1_BYTES>>>(hist, target, aW1, ab1, aW2, ab2);
    din_mlp<<<BB / 32, 256, SM2_BYTES>>>(target, other, oW1, ob1, oW2, ob2,
                                         oW3, ob3, fW, fb, out);
}

// round 9
// speedup vs baseline: 1.2007x; 1.2007x over previous
#include <cuda_runtime.h>
#include <cuda_fp16.h>
#include <math.h>

#define BB     8192
#define MM     200
#define EE     64
#define NOTHER 128
#define H1     96
#define F1     128
#define F2     85
#define F3     64

__device__ float g_tmp[BB * EE];

// ---------------- Kernel 1: attention + weighted sum ----------------
// smem u32: W2 3328, hist 7488; floats: tgt 64, c 96, w2 96, aij 208, part 512
#define SM1_U32  (3328 + 7488 + 64 + 96 + 96 + 208 + 512)
#define SM1_BYTES (SM1_U32 * 4)

__global__ __launch_bounds__(256, 4)
void din_attn(const float* __restrict__ hist, const float* __restrict__ target,
              const float* __restrict__ aW1, const float* __restrict__ ab1,
              const float* __restrict__ aW2, const float* __restrict__ ab2)
{
    extern __shared__ unsigned sm1[];
    unsigned* s_W2 = sm1;                 // half2 W1eff [k2*104 + n]
    unsigned* s_h  = sm1 + 3328;          // half2 hist  [row*36 + k2]
    float* s_tgt  = (float*)(sm1 + 3328 + 7488);
    float* s_c    = s_tgt + 64;
    float* s_w2   = s_c + 96;
    float* s_aij  = s_w2 + 96;
    float* s_part = s_aij + 208;          // [8][64]

    const int b = blockIdx.x;
    const int t = threadIdx.x;
    const float* hb = hist + (size_t)b * MM * EE;

    if (t < EE) s_tgt[t] = target[(size_t)b * EE + t];
    if (t < H1) s_w2[t]  = aW2[t];
    __syncthreads();

    for (int idx = t; idx < MM * 16; idx += 256) {
        const int row = idx >> 4, q = idx & 15;
        float4 v = ((const float4*)(hb + (size_t)row * EE))[q];
        __half2 h01 = __floats2half2_rn(v.x, v.y);
        __half2 h23 = __floats2half2_rn(v.z, v.w);
        uint2 st;
        st.x = *(unsigned*)&h01;
        st.y = *(unsigned*)&h23;
        *(uint2*)(s_h + row * 36 + 2 * q) = st;
    }
    for (int idx = t; idx < 8 * 36; idx += 256)
        s_h[200 * 36 + idx] = 0u;

    for (int idx = t; idx < 32 * H1; idx += 256) {
        const int k2 = idx / H1, n = idx - k2 * H1;
        const int e0 = 2 * k2, e1 = 2 * k2 + 1;
        float v0 = aW1[e0 * H1 + n] + s_tgt[e0] * aW1[(EE + e0) * H1 + n];
        float v1 = aW1[e1 * H1 + n] + s_tgt[e1] * aW1[(EE + e1) * H1 + n];
        __half2 p = __floats2half2_rn(v0, v1);
        s_W2[k2 * 104 + n] = *(unsigned*)&p;
    }
    if (t < H1) {
        float acc = ab1[t];
        #pragma unroll 8
        for (int e = 0; e < EE; e++)
            acc = fmaf(s_tgt[e], aW1[(2 * EE + e) * H1 + t], acc);
        s_c[t] = acc;
    }
    __syncthreads();

    const int warp = t >> 5, lane = t & 31;
    const int gid = lane >> 2, tig = lane & 3;
    const float bias2 = ab2[0];

    for (int mt = warp; mt < 13; mt += 8) {
        unsigned A[4][4];
        const unsigned* hp = s_h + (mt * 16 + gid) * 36 + tig;
        #pragma unroll
        for (int ks = 0; ks < 4; ks++) {
            A[ks][0] = hp[8 * ks];
            A[ks][1] = hp[288 + 8 * ks];
            A[ks][2] = hp[8 * ks + 4];
            A[ks][3] = hp[288 + 8 * ks + 4];
        }

        float aij0 = 0.f, aij1 = 0.f;
        const unsigned* wb = s_W2 + tig * 104 + gid;

        #pragma unroll 1
        for (int nt = 0; nt < 12; nt++) {
            float c0 = 0.f, c1 = 0.f, c2 = 0.f, c3 = 0.f;
            #pragma unroll
            for (int ks = 0; ks < 4; ks++) {
                const unsigned b0 = wb[ks * 832 + nt * 8];
                const unsigned b1 = wb[ks * 832 + 416 + nt * 8];
                asm volatile(
                    "mma.sync.aligned.m16n8k16.row.col.f32.f16.f16.f32 "
                    "{%0,%1,%2,%3}, {%4,%5,%6,%7}, {%8,%9}, {%0,%1,%2,%3};"
                    : "+f"(c0), "+f"(c1), "+f"(c2), "+f"(c3)
                    : "r"(A[ks][0]), "r"(A[ks][1]), "r"(A[ks][2]), "r"(A[ks][3]),
                      "r"(b0), "r"(b1));
            }
            const int j0 = nt * 8 + 2 * tig;
            const float cc0 = s_c[j0],  cc1 = s_c[j0 + 1];
            const float w0  = s_w2[j0], w1  = s_w2[j0 + 1];
            aij0 = fmaf(fmaxf(c0 + cc0, 0.f), w0, aij0);
            aij0 = fmaf(fmaxf(c1 + cc1, 0.f), w1, aij0);
            aij1 = fmaf(fmaxf(c2 + cc0, 0.f), w0, aij1);
            aij1 = fmaf(fmaxf(c3 + cc1, 0.f), w1, aij1);
        }
        aij0 += __shfl_xor_sync(0xffffffffu, aij0, 1);
        aij0 += __shfl_xor_sync(0xffffffffu, aij0, 2);
        aij1 += __shfl_xor_sync(0xffffffffu, aij1, 1);
        aij1 += __shfl_xor_sync(0xffffffffu, aij1, 2);
        if (tig == 0) {
            const int r0 = mt * 16 + gid;
            if (r0 < MM)     s_aij[r0]     = aij0 + bias2;
            if (r0 + 8 < MM) s_aij[r0 + 8] = aij1 + bias2;
        }
    }
    __syncthreads();

    // ---- Phase 2: tmp[e] = sum_m aij[m]*hist[m][e]  from fp16 smem (LDS, conflict-free) ----
    {
        const int chunk = warp;          // 8 chunks x 25 rows
        const int e2 = lane;             // half2 index 0..31 -> e = 2*e2, 2*e2+1
        const int m0 = chunk * 25;
        float acc0 = 0.f, acc1 = 0.f;
        #pragma unroll 5
        for (int m = m0; m < m0 + 25; m++) {
            const unsigned u = s_h[m * 36 + e2];
            const __half2 h = *(const __half2*)&u;
            const float2 f = __half22float2(h);
            const float a = s_aij[m];
            acc0 = fmaf(a, f.x, acc0);
            acc1 = fmaf(a, f.y, acc1);
        }
        float2 st; st.x = acc0; st.y = acc1;
        *(float2*)(s_part + chunk * 64 + 2 * e2) = st;
    }
    __syncthreads();
    if (t < EE) {
        float v = 0.f;
        #pragma unroll
        for (int c = 0; c < 8; c++)
            v += s_part[c * 64 + t];
        g_tmp[(size_t)b * EE + t] = v;
    }
}

// ---------------- Kernel 2: MLP (exact R7 version — 2 batches/warp, grid 512) ----------------
#define NB   16
#define MX   (NB * 256)
#define MH1  (NB * F1)
#define MH2  (NB * 88)
#define SM2_BYTES ((MX + MH1 + MH2) * 4)

__global__ __launch_bounds__(256)
void din_mlp(const float* __restrict__ target, const float* __restrict__ other,
             const float* __restrict__ oW1, const float* __restrict__ ob1,
             const float* __restrict__ oW2, const float* __restrict__ ob2,
             const float* __restrict__ oW3, const float* __restrict__ ob3,
             const float* __restrict__ fW,  const float* __restrict__ fb,
             float* __restrict__ out)
{
    extern __shared__ float sm2[];
    float* s_x  = sm2;
    float* s_h1 = sm2 + MX;
    float* s_h2 = sm2 + MX + MH1;

    const int t = threadIdx.x;
    const int B0 = blockIdx.x * NB;

    for (int idx = t; idx < NB * 16; idx += 256) {
        const int bi = idx >> 4, q = idx & 15;
        float4 v = ((const float4*)(g_tmp + (size_t)(B0 + bi) * EE))[q];
        *(float4*)(s_x + bi * 256 + 4 * q) = v;
        float4 u = ((const float4*)(target + (size_t)(B0 + bi) * EE))[q];
        *(float4*)(s_x + bi * 256 + 64 + 4 * q) = u;
    }
    for (int idx = t; idx < NB * 32; idx += 256) {
        const int bi = idx >> 5, q = idx & 31;
        float4 v = ((const float4*)(other + (size_t)(B0 + bi) * NOTHER))[q];
        *(float4*)(s_x + bi * 256 + 128 + 4 * q) = v;
    }
    __syncthreads();

    const int warp = t >> 5, lane = t & 31;
    const int wb = warp * 2;
    const float* x0 = s_x + (wb + 0) * 256;
    const float* x1 = s_x + (wb + 1) * 256;

    {
        const int j0 = lane * 4;
        float4 bv = *(const float4*)(ob1 + j0);
        float a0x = bv.x, a0y = bv.y, a0z = bv.z, a0w = bv.w;
        float a1x = bv.x, a1y = bv.y, a1z = bv.z, a1w = bv.w;
        #pragma unroll 4
        for (int k = 0; k < 256; k += 4) {
            const float4 v0 = *(const float4*)(x0 + k);
            const float4 v1 = *(const float4*)(x1 + k);
            #pragma unroll
            for (int i = 0; i < 4; i++) {
                const float4 w = *(const float4*)(oW1 + (k + i) * F1 + j0);
                const float e0 = (i == 0) ? v0.x : (i == 1) ? v0.y : (i == 2) ? v0.z : v0.w;
                const float e1 = (i == 0) ? v1.x : (i == 1) ? v1.y : (i == 2) ? v1.z : v1.w;
                a0x = fmaf(e0, w.x, a0x); a0y = fmaf(e0, w.y, a0y);
                a0z = fmaf(e0, w.z, a0z); a0w = fmaf(e0, w.w, a0w);
                a1x = fmaf(e1, w.x, a1x); a1y = fmaf(e1, w.y, a1y);
                a1z = fmaf(e1, w.z, a1z); a1w = fmaf(e1, w.w, a1w);
            }
        }
        float4 r;
        r.x = fmaxf(a0x, 0.f); r.y = fmaxf(a0y, 0.f); r.z = fmaxf(a0z, 0.f); r.w = fmaxf(a0w, 0.f);
        *(float4*)(s_h1 + (wb + 0) * F1 + j0) = r;
        r.x = fmaxf(a1x, 0.f); r.y = fmaxf(a1y, 0.f); r.z = fmaxf(a1z, 0.f); r.w = fmaxf(a1w, 0.f);
        *(float4*)(s_h1 + (wb + 1) * F1 + j0) = r;
    }
    __syncwarp();

    const float* h10 = s_h1 + (wb + 0) * F1;
    const float* h11 = s_h1 + (wb + 1) * F1;

    {
        const int j2 = lane + 64;
        const bool g2 = (j2 < F2);
        float b0 = ob2[lane], b1 = ob2[lane + 32], b2 = g2 ? ob2[j2] : 0.f;
        float a00 = b0, a01 = b1, a02 = b2;
        float a10 = b0, a11 = b1, a12 = b2;
        #pragma unroll 4
        for (int k = 0; k < F1; k += 4) {
            const float4 v0 = *(const float4*)(h10 + k);
            const float4 v1 = *(const float4*)(h11 + k);
            #pragma unroll
            for (int i = 0; i < 4; i++) {
                const float* wr = oW2 + (k + i) * F2;
                const float w0 = wr[lane];
                const float w1 = wr[lane + 32];
                const float w2 = g2 ? wr[j2] : 0.f;
                const float e0 = (i == 0) ? v0.x : (i == 1) ? v0.y : (i == 2) ? v0.z : v0.w;
                const float e1 = (i == 0) ? v1.x : (i == 1) ? v1.y : (i == 2) ? v1.z : v1.w;
                a00 = fmaf(e0, w0, a00); a01 = fmaf(e0, w1, a01); a02 = fmaf(e0, w2, a02);
                a10 = fmaf(e1, w0, a10); a11 = fmaf(e1, w1, a11); a12 = fmaf(e1, w2, a12);
            }
        }
        s_h2[(wb + 0) * 88 + lane]      = fmaxf(a00, 0.f);
        s_h2[(wb + 0) * 88 + lane + 32] = fmaxf(a01, 0.f);
        s_h2[(wb + 1) * 88 + lane]      = fmaxf(a10, 0.f);
        s_h2[(wb + 1) * 88 + lane + 32] = fmaxf(a11, 0.f);
        if (g2) {
            s_h2[(wb + 0) * 88 + j2] = fmaxf(a02, 0.f);
            s_h2[(wb + 1) * 88 + j2] = fmaxf(a12, 0.f);
        }
    }
    __syncwarp();

    {
        const float b0 = ob3[lane], b1 = ob3[lane + 32];
        float a00 = b0, a01 = b1;
        float a10 = b0, a11 = b1;
        const float* h20 = s_h2 + (wb + 0) * 88;
        const float* h21 = s_h2 + (wb + 1) * 88;
        #pragma unroll 5
        for (int k = 0; k < F2; k++) {
            const float w0 = oW3[k * F3 + lane];
            const float w1 = oW3[k * F3 + lane + 32];
            const float v0 = h20[k], v1 = h21[k];
            a00 = fmaf(v0, w0, a00); a01 = fmaf(v0, w1, a01);
            a10 = fmaf(v1, w0, a10); a11 = fmaf(v1, w1, a11);
        }
        const float f0 = fW[lane], f1 = fW[lane + 32];
        float v0 = fmaxf(a00, 0.f) * f0 + fmaxf(a01, 0.f) * f1;
        float v1 = fmaxf(a10, 0.f) * f0 + fmaxf(a11, 0.f) * f1;
        #pragma unroll
        for (int off = 16; off; off >>= 1) {
            v0 += __shfl_xor_sync(0xffffffffu, v0, off);
            v1 += __shfl_xor_sync(0xffffffffu, v1, off);
        }
        if (lane == 0) {
            const float fbv = fb[0];
            out[B0 + wb + 0] = 1.f / (1.f + expf(-(v0 + fbv)));
            out[B0 + wb + 1] = 1.f / (1.f + expf(-(v1 + fbv)));
        }
    }
}

extern "C" void kernel_launch(void* const* d_in, const int* in_sizes, int n_in,
                              void* d_out, int out_size)
{
    const float* hist   = (const float*)d_in[0];
    const float* target = (const float*)d_in[1];
    const float* other  = (const float*)d_in[2];
    const float* aW1    = (const float*)d_in[3];
    const float* ab1    = (const float*)d_in[4];
    const float* aW2    = (const float*)d_in[5];
    const float* ab2    = (const float*)d_in[6];
    const float* oW1    = (const float*)d_in[7];
    const float* ob1    = (const float*)d_in[8];
    const float* oW2    = (const float*)d_in[9];
    const float* ob2    = (const float*)d_in[10];
    const float* oW3    = (const float*)d_in[11];
    const float* ob3    = (const float*)d_in[12];
    const float* fW     = (const float*)d_in[13];
    const float* fb     = (const float*)d_in[14];
    float* out = (float*)d_out;

    static int configured = 0;
    if (!configured) {
        cudaFuncSetAttribute(din_mlp, cudaFuncAttributeMaxDynamicSharedMemorySize,
                             SM2_BYTES);
        configured = 1;
    }
    din_attn<<<BB, 256, SM1_BYTES>>>(hist, target, aW1, ab1, aW2, ab2);
    din_mlp<<<BB / NB, 256, SM2_BYTES>>>(target, other, oW1, ob1, oW2, ob2,
                                         oW3, ob3, fW, fb, out);
}